// round 10
// baseline (speedup 1.0000x reference)
#include <cuda_runtime.h>
#include <math.h>

#define NPART 4096
#define MAXNB 48

// ---------------- device scratch (no allocations allowed) ----------------
__device__ float2         g_p0[NPART];            // pos + trans (collision input)
__device__ unsigned short g_nb16[NPART * MAXNB];  // candidate lists (uint16 idx, 96B rows)
__device__ int            g_ncnt[NPART];

// ---------------- constants (match reference float32 semantics) ----------
#define PI_F      3.1415927410125732f
#define TWO_PI_F  6.2831854820251465f

__device__ __forceinline__ float wrapf(float diff) {
    // matches: where(diff <= -pi, mod(diff, pi), diff); then -2pi if >= pi
    if (diff <= -PI_F) {
        float m = fmodf(diff, PI_F);       // C fmod: sign of dividend
        if (m < 0.0f) m += PI_F;           // -> pythonic mod in [0, pi)
        diff = m;
    }
    if (diff >= PI_F) diff -= TWO_PI_F;
    return diff;
}

// ---------------- K1: N^2 pair pass + per-particle epilogue ----------------
// One warp per particle. 128 blocks x 32 warps = 4096 particles.
__global__ void __launch_bounds__(1024) k_main(
    const float* __restrict__ pre, const float* __restrict__ pim,
    const float* __restrict__ ore, const float* __restrict__ oim,
    const float* __restrict__ deltas, const float* __restrict__ rotn,
    const float* __restrict__ tnr, const float* __restrict__ tni,
    float* __restrict__ out)
{
    const float RO_RC2 = (float)(2.815e-5 * 2.815e-5);   // (RO+RC)^2
    const float RR2    = (float)(8.0e-6 * 8.0e-6);       // RR^2
    const float NB2    = (float)(2.52e-5 * 2.52e-5);     // (8*RC)^2 candidate radius

    __shared__ float2 spos[NPART];   // 32 KB: whole system
    __shared__ float  swx[32], swy[32];
    __shared__ float2 smean;

    int t    = threadIdx.x;
    int warp = t >> 5;
    int lane = t & 31;

    // stage positions + partial mean sums
    float ax = 0.f, ay = 0.f;
#pragma unroll
    for (int k = 0; k < 4; k++) {
        int idx = t + 1024 * k;
        float x = pre[idx], y = pim[idx];
        spos[idx] = make_float2(x, y);
        ax += x; ay += y;
    }
#pragma unroll
    for (int o = 16; o > 0; o >>= 1) {
        ax += __shfl_down_sync(0xffffffffu, ax, o);
        ay += __shfl_down_sync(0xffffffffu, ay, o);
    }
    if (lane == 0) { swx[warp] = ax; swy[warp] = ay; }
    __syncthreads();
    if (warp == 0) {
        float bx = swx[lane], by = swy[lane];
#pragma unroll
        for (int o = 16; o > 0; o >>= 1) {
            bx += __shfl_down_sync(0xffffffffu, bx, o);
            by += __shfl_down_sync(0xffffffffu, by, o);
        }
        if (lane == 0) smean = make_float2(bx * (1.0f / 4096.0f), by * (1.0f / 4096.0f));
    }
    __syncthreads();

    int i = blockIdx.x * 32 + warp;
    float2 pi_ = spos[i];
    float  orx = __ldg(&ore[i]), ory = __ldg(&oim[i]);

    float osr = 0.f, osi = 0.f, sx = 0.f, sy = 0.f;
    int nr = 0, cnt = 0;
    unsigned lmask = (1u << lane) - 1u;
    const float4* sp4 = reinterpret_cast<const float4*>(spos);

#pragma unroll 4
    for (int jj = lane; jj < NPART / 2; jj += 32) {
        float4 v = sp4[jj];                    // particles 2jj, 2jj+1
        int jA = 2 * jj, jB = 2 * jj + 1;
        float dxA = v.x - pi_.x, dyA = v.y - pi_.y;
        float dxB = v.z - pi_.x, dyB = v.w - pi_.y;
        float d2A = fmaf(dxA, dxA, dyA * dyA);
        float d2B = fmaf(dxB, dxB, dyB * dyB);
        bool roA = (d2A <= RO_RC2), roB = (d2B <= RO_RC2);
        unsigned mro = __ballot_sync(0xffffffffu, roA || roB);
        if (mro) {   // rare branch (~9% of iterations), warp-uniform
            bool nbA = roA && (d2A <= NB2) && (jA != i);
            bool nbB = roB && (d2B <= NB2) && (jB != i);
            unsigned mA = __ballot_sync(0xffffffffu, nbA);
            unsigned mB = __ballot_sync(0xffffffffu, nbB);
            if (nbA) {
                int idx = cnt + __popc(mA & lmask);
                if (idx < MAXNB) g_nb16[i * MAXNB + idx] = (unsigned short)jA;
            }
            cnt += __popc(mA);
            if (nbB) {
                int idx = cnt + __popc(mB & lmask);
                if (idx < MAXNB) g_nb16[i * MAXNB + idx] = (unsigned short)jB;
            }
            cnt += __popc(mB);
            if (roA) {
                float ojx = __ldg(&ore[jA]), ojy = __ldg(&oim[jA]);
                osr += ojx; osi += ojy;
                if (d2A <= RR2 && jA != i) {
                    // |wrap(ang_i-ang_j)| < pi/2  <=>  dot(ori_i, ori_j) > 0
                    if (orx * ojx + ory * ojy > 0.0f) { nr += 1; sx += v.x; sy += v.y; }
                }
            }
            if (roB) {
                float ojx = __ldg(&ore[jB]), ojy = __ldg(&oim[jB]);
                osr += ojx; osi += ojy;
                if (d2B <= RR2 && jB != i) {
                    if (orx * ojx + ory * ojy > 0.0f) { nr += 1; sx += v.z; sy += v.w; }
                }
            }
        }
    }

    // warp reduction
#pragma unroll
    for (int o = 16; o > 0; o >>= 1) {
        osr += __shfl_down_sync(0xffffffffu, osr, o);
        osi += __shfl_down_sync(0xffffffffu, osi, o);
        sx  += __shfl_down_sync(0xffffffffu, sx,  o);
        sy  += __shfl_down_sync(0xffffffffu, sy,  o);
        nr  += __shfl_down_sync(0xffffffffu, nr,  o);
    }

    if (lane == 0) {
        g_ncnt[i] = (cnt < MAXNB) ? cnt : MAXNB;

        float angi = atan2f(ory, orx);
        float2 mean = smean;
        float invn = 1.0f / fmaxf((float)nr, 1.0f);
        float sgn  = (nr > 0) ? 1.0f : 0.0f;
        float Sx = sx * invn - pi_.x * sgn;
        float Sy = sy * invn - pi_.y * sgn;
        float dxr = -Sx, dyr = -Sy;

        float Psx = mean.x - pi_.x;
        float Psy = mean.y - pi_.y;

        float del = deltas[i];
        float cd, sd; sincosf(del, &sd, &cd);
        float lx = Psx * cd - Psy * sd;            // Ps * exp(+i delta)
        float ly = Psx * sd + Psy * cd;
        float rx = Psx * cd + Psy * sd;            // Ps * exp(-i delta)
        float ry = Psy * cd - Psx * sd;

        float no  = fmaxf(sqrtf(osr * osr + osi * osi), 1e-14f);
        float nl  = fmaxf(sqrtf(lx * lx + ly * ly), 1e-14f);
        float nrt = fmaxf(sqrtf(rx * rx + ry * ry), 1e-14f);
        float csl = (lx * osr + ly * osi) / (nl * no);
        float csr = (rx * osr + ry * osi) / (nrt * no);
        float bx = (csl >= csr) ? lx : rx;
        float by = (csl >= csr) ? ly : ry;

        bool hasrep = (dxr * dxr + dyr * dyr) > 0.0f;
        float aa  = hasrep ? atan2f(dyr, dxr) : atan2f(by, bx);
        float att = wrapf(aa - angi);

        float theta = 0.014f * sinf(att)
                    + (rotn[i] * 0.074833147735478508f) * 0.44721359549995793f;
        float cr, sr; sincosf(theta, &sr, &cr);
        float nor = orx * cr - ory * sr;           // new_ori = ori * rot
        float noi = orx * sr + ory * cr;

        float tnx = ((tnr[i] * 0.70710678118654752f) * 1.6733200530681511e-7f)
                    * 0.44721359549995793f;
        float tny = ((tni[i] * 0.70710678118654752f) * 1.6733200530681511e-7f)
                    * 0.44721359549995793f;
        float trx = 1e-7f * orx + tnx;             // DT*VEL*ori + tnoise*sqrt(DT)
        float try_ = 1e-7f * ory + tny;

        g_p0[i] = make_float2(pi_.x + trx, pi_.y + try_);

        out[ 8192 + 2 * i]     = nor;  out[ 8192 + 2 * i + 1] = noi;  // new_ori
        out[16384 + 2 * i]     = osr;  out[16384 + 2 * i + 1] = osi;  // osum
        out[24576 + 2 * i]     = lx;   out[24576 + 2 * i + 1] = ly;   // left
        out[32768 + 2 * i]     = rx;   out[32768 + 2 * i + 1] = ry;   // right
    }
}

// ---------------- K2: collision solve, warp-cooperative stamping -----------
// Mark-scan compute (epoch stamps), movers collected into a shared list, and
// the candidate-list stamping is done warp-per-mover (breaks the serial
// per-mover stamp chain that dominated previous rounds). 2 barriers/iter.
__global__ void __launch_bounds__(1024) k_collide(float* __restrict__ out) {
    __shared__ float2         sp[NPART];       // 32 KB positions
    __shared__ unsigned char  mark[NPART];     // 4 KB epoch stamps
    __shared__ unsigned short midx[NPART];     // 8 KB mover list (order irrelevant)
    __shared__ int            nmv[2];          // double-buffered mover counter

    int t = threadIdx.x;
    int warp = t >> 5;
    int lane = t & 31;
    unsigned lmask = (1u << lane) - 1u;

#pragma unroll
    for (int k = 0; k < 4; k++) {
        int i = t + 1024 * k;
        sp[i] = g_p0[i];
        mark[i] = 0;                           // everyone active at iteration 0
    }
    if (t == 0) { nmv[0] = 0; nmv[1] = 0; }
    __syncthreads();

    const float C2  = (float)(6.3e-6 * 6.3e-6);   // (2*RC)^2
    const float TRC = 6.615e-6f;                  // 2.1*RC

    for (int it = 0; it < 30; it++) {
        int cb = it & 1;
        unsigned char ep = (unsigned char)it;
        bool moved_any = false;
        float2 newp[4];
        unsigned mvk = 0;                      // bitmask: which k-slots moved

        // ---- compute phase: mark-scan, MLP-4 neighbor loads ----
#pragma unroll
        for (int k = 0; k < 4; k++) {
            int i = t + 1024 * k;
            bool active = (mark[i] == ep);
            int c = active ? g_ncnt[i] : 0;    // L1-hot
            bool m = false;
            if (c > 0) {
                float2 p = sp[i];
                float ax = 0.f, ay = 0.f;
                const unsigned* nbp = reinterpret_cast<const unsigned*>(&g_nb16[i * MAXNB]);
                for (int q = 0; q < c; q += 4) {
                    unsigned wA = nbp[(q >> 1)];
                    unsigned wB = nbp[(q >> 1) + 1];
                    int j0 = wA & 4095, j1 = (wA >> 16) & 4095;
                    int j2 = wB & 4095, j3 = (wB >> 16) & 4095;
                    float2 p0 = sp[j0], p1 = sp[j1], p2 = sp[j2], p3 = sp[j3];
#pragma unroll
                    for (int r = 0; r < 4; r++) {
                        if (q + r < c) {
                            float2 pj = (r == 0) ? p0 : (r == 1) ? p1 : (r == 2) ? p2 : p3;
                            float dx = pj.x - p.x;
                            float dy = pj.y - p.y;
                            float d2 = dx * dx + dy * dy;
                            if (d2 <= C2) {
                                float dd = sqrtf(d2);
                                float sc = (TRC - dd) * 0.5f / dd;
                                ax += dx * sc; ay += dy * sc;
                                m = true;
                            }
                        }
                    }
                }
                if (m) {
                    newp[k] = make_float2(p.x - ax, p.y - ay);
                    mvk |= (1u << k);
                    moved_any = true;
                }
            }
            // warp-aggregated append of mover id (uniform ballot, order irrelevant)
            unsigned mb = __ballot_sync(0xffffffffu, m);
            if (mb) {
                int leader = __ffs(mb) - 1;
                int base = 0;
                if (lane == leader) base = atomicAdd(&nmv[cb], __popc(mb));
                base = __shfl_sync(0xffffffffu, base, leader);
                if (m) midx[base + __popc(mb & lmask)] = (unsigned short)i;
            }
        }

        int tot = __syncthreads_count(moved_any ? 1 : 0);   // all sp/mark reads done
        if (tot == 0) break;          // no collisions anywhere -> fixed point (== ref cont)

        int total = nmv[cb];          // final: all appends preceded the barrier
        unsigned char epn = (unsigned char)(it + 1);

        // ---- apply phase: own positions from registers (cheap) ----
#pragma unroll
        for (int k = 0; k < 4; k++) {
            if ((mvk >> k) & 1u) sp[t + 1024 * k] = newp[k];
        }
        // ---- stamp phase: warp-per-mover (parallel over candidate list) ----
        for (int m = warp; m < total; m += 32) {
            int i = (int)midx[m];
            if (lane == 0) mark[i] = epn;
            int c = g_ncnt[i];
            const unsigned short* nb = &g_nb16[i * MAXNB];
            for (int q = lane; q < c; q += 32)
                mark[nb[q]] = epn;             // benign same-value races
        }
        if (t == 0) nmv[(it + 1) & 1] = 0;     // reset buffer for next iteration
        __syncthreads();                       // sp/mark writes visible
    }

#pragma unroll
    for (int k = 0; k < 4; k++) {
        int i = t + 1024 * k;
        out[2 * i]     = sp[i].x;
        out[2 * i + 1] = sp[i].y;
    }
}

// ---------------- launch ----------------------------------------------------
extern "C" void kernel_launch(void* const* d_in, const int* in_sizes, int n_in,
                              void* d_out, int out_size) {
    const float* pre = (const float*)d_in[0];
    const float* pim = (const float*)d_in[1];
    const float* ore = (const float*)d_in[2];
    const float* oim = (const float*)d_in[3];
    const float* del = (const float*)d_in[4];
    const float* rn  = (const float*)d_in[5];
    const float* tnr = (const float*)d_in[6];
    const float* tni = (const float*)d_in[7];
    float* out = (float*)d_out;

    k_main<<<128, 1024>>>(pre, pim, ore, oim, del, rn, tnr, tni, out);
    k_collide<<<1, 1024>>>(out);
}